// round 13
// baseline (speedup 1.0000x reference)
#include <cuda_runtime.h>
#include <cstdint>

typedef unsigned long long u64;
#define DEV static __device__ __forceinline__

static constexpr int L_ = 3;
static constexpr int NB = 128;    // physical CTAs
static constexpr int NBV = 256;   // virtual CTAs (2 per physical), 4 rows each
static constexpr int NT = 512;

// ---------------- device globals ----------------
__device__ float g_P[2][1024 * 128];   // double-buffered Pj
__device__ float g_Wc[L_][128 * 128];  // ew2 @ nw1b
__device__ float g_cb[L_][128];        // eb2 @ nw1b
__device__ unsigned g_bar[4];          // monotonic barrier counters (replay-safe)

// ---------------- f32x2 helpers ----------------
DEV u64 pk(float lo, float hi) {
    u64 r; asm("mov.b64 %0,{%1,%2};" : "=l"(r) : "f"(lo), "f"(hi)); return r;
}
DEV void upk(u64 v, float& lo, float& hi) {
    asm("mov.b64 {%0,%1},%2;" : "=f"(lo), "=f"(hi) : "l"(v));
}
DEV u64 add2(u64 a, u64 b) {
    u64 r; asm("add.rn.f32x2 %0,%1,%2;" : "=l"(r) : "l"(a), "l"(b)); return r;
}
DEV u64 fma2(u64 a, u64 b, u64 c) {
    u64 r; asm("fma.rn.f32x2 %0,%1,%2,%3;" : "=l"(r) : "l"(a), "l"(b), "l"(c)); return r;
}
DEV u64 relu2(u64 v) {
    float lo, hi; upk(v, lo, hi);
    return pk(fmaxf(lo, 0.f), fmaxf(hi, 0.f));
}

// ---------------- half-CTA named barrier ----------------
DEV void barh(int half) {
    asm volatile("bar.sync %0, 256;" :: "r"(half + 1) : "memory");
}

// ---------------- virtual grid barrier (256 arrivals; replay-safe) ----------------
DEV unsigned ld_acq(const unsigned* p) {
    unsigned v;
    asm volatile("ld.acquire.gpu.global.u32 %0,[%1];" : "=r"(v) : "l"(p) : "memory");
    return v;
}
DEV void vbar_arrive(int bidx, int th, int half, unsigned& tgt) {
    barh(half);                       // all half's prior work done
    if (th == 0) {
        __threadfence();
        unsigned t = atomicAdd(&g_bar[bidx], 1u);
        tgt = (t / (unsigned)NBV + 1u) * (unsigned)NBV;
    }
}
DEV void vbar_wait(int bidx, int th, int half, unsigned tgt) {
    barh(half);                       // interim work done
    if (th == 0) {
        while (ld_acq(&g_bar[bidx]) < tgt) { __nanosleep(64); }
        __threadfence();
    }
    barh(half);
}

// ---------------- per-half GEMM: 4 rows x 128 cols, k-split-8 (W via __ldg) ------
// warp kq = wh (0..7), 16 k each; lane = 4 cols.
// dup'd A: ATs[k*12 + 2r] = ATs[k*12+2r+1] = A[r][k]  (r < 4)
DEV void gemm_h(const float* __restrict__ ATs, const float* __restrict__ W,
                int lane, int kq, u64 acc[4][2]) {
    const float* ap = ATs + kq * 16 * 12;
    const float* wp = W + kq * 16 * 128 + lane * 4;
#pragma unroll
    for (int k = 0; k < 16; k++) {
        ulonglong2 wv = __ldg((const ulonglong2*)(wp + k * 128));
        ulonglong2 a01 = *(const ulonglong2*)(ap + k * 12);
        ulonglong2 a23 = *(const ulonglong2*)(ap + k * 12 + 4);
        acc[0][0] = fma2(a01.x, wv.x, acc[0][0]);
        acc[0][1] = fma2(a01.x, wv.y, acc[0][1]);
        acc[1][0] = fma2(a01.y, wv.x, acc[1][0]);
        acc[1][1] = fma2(a01.y, wv.y, acc[1][1]);
        acc[2][0] = fma2(a23.x, wv.x, acc[2][0]);
        acc[2][1] = fma2(a23.x, wv.y, acc[2][1]);
        acc[3][0] = fma2(a23.y, wv.x, acc[3][0]);
        acc[3][1] = fma2(a23.y, wv.y, acc[3][1]);
    }
}

// per-half merged GEMM: 4 rows x 256 cols, warp=(cg2, kq4), 32 k each
DEV void gemm_mh(const float* __restrict__ ATs, const float* __restrict__ W,
                 int lane, int kq, u64 acc[4][2]) {
    const float* ap = ATs + kq * 32 * 12;
    const float* wp = W + kq * 32 * 128 + lane * 4;
#pragma unroll 16
    for (int k = 0; k < 32; k++) {
        ulonglong2 wv = __ldg((const ulonglong2*)(wp + k * 128));
        ulonglong2 a01 = *(const ulonglong2*)(ap + k * 12);
        ulonglong2 a23 = *(const ulonglong2*)(ap + k * 12 + 4);
        acc[0][0] = fma2(a01.x, wv.x, acc[0][0]);
        acc[0][1] = fma2(a01.x, wv.y, acc[0][1]);
        acc[1][0] = fma2(a01.y, wv.x, acc[1][0]);
        acc[1][1] = fma2(a01.y, wv.y, acc[1][1]);
        acc[2][0] = fma2(a23.x, wv.x, acc[2][0]);
        acc[2][1] = fma2(a23.x, wv.y, acc[2][1]);
        acc[3][0] = fma2(a23.y, wv.x, acc[3][0]);
        acc[3][1] = fma2(a23.y, wv.y, acc[3][1]);
    }
}

DEV void store_part_h(float* sPart, const u64 acc[4][2], int lane, int kq) {
    float* o = sPart + kq * 512 + lane * 4;
#pragma unroll
    for (int r = 0; r < 4; r++) {
        float v0, v1, v2, v3;
        upk(acc[r][0], v0, v1); upk(acc[r][1], v2, v3);
        *(float4*)(o + r * 128) = make_float4(v0, v1, v2, v3);
    }
}

DEV float reduce8_h(const float* __restrict__ sPart, int idx) {
    float v = 0.f;
#pragma unroll
    for (int p = 0; p < 8; p++) v += sPart[p * 512 + idx];
    return v;
}

// per-half agg: warp jq = wh, 32 j each; 4 i x 4 d per lane; Pj via LDG.cg
DEV void agg_h(const float* __restrict__ Pjb, const float* __restrict__ sAdj2,
               const u64 xi[4][2], u64 acc[4][2], int lane, int jq) {
    const float* pj = Pjb + jq * 32 * 128 + lane * 4;
    const float* ad = sAdj2 + jq * 32 * 8;
#pragma unroll 8
    for (int jj = 0; jj < 32; jj++) {
        ulonglong2 xj = __ldcg((const ulonglong2*)(pj + jj * 128));
        ulonglong2 a01 = *(const ulonglong2*)(ad + jj * 8);      // (dup a_i0, dup a_i1)
        ulonglong2 a23 = *(const ulonglong2*)(ad + jj * 8 + 4);  // (dup a_i2, dup a_i3)
        u64 t;
        t = relu2(add2(xi[0][0], xj.x)); acc[0][0] = fma2(t, a01.x, acc[0][0]);
        t = relu2(add2(xi[0][1], xj.y)); acc[0][1] = fma2(t, a01.x, acc[0][1]);
        t = relu2(add2(xi[1][0], xj.x)); acc[1][0] = fma2(t, a01.y, acc[1][0]);
        t = relu2(add2(xi[1][1], xj.y)); acc[1][1] = fma2(t, a01.y, acc[1][1]);
        t = relu2(add2(xi[2][0], xj.x)); acc[2][0] = fma2(t, a23.x, acc[2][0]);
        t = relu2(add2(xi[2][1], xj.y)); acc[2][1] = fma2(t, a23.x, acc[2][1]);
        t = relu2(add2(xi[3][0], xj.x)); acc[3][0] = fma2(t, a23.y, acc[3][0]);
        t = relu2(add2(xi[3][1], xj.y)); acc[3][1] = fma2(t, a23.y, acc[3][1]);
    }
}

// ---------------- per-half smem (floats): total 10752 per half ----------------
// sATs 0 (1536) | sNTs 1536 (1536) | sPart 3072 (4096) | sPi 7168 (512)
// sPn 7680 (512) | sAdj2 8192 (2048) | s_rs 10240 (8) | sX 10248 (512)
static constexpr int HALF_FLOATS = 10760;
static constexpr int SMEM_FLOATS = 2 * HALF_FLOATS;   // 86080 B

__global__ void __launch_bounds__(NT, 1) k_main(
    float* __restrict__ x, const float* __restrict__ nf, const float* __restrict__ adj,
    const float* __restrict__ ew1, const float* __restrict__ eb1,
    const float* __restrict__ ew2, const float* __restrict__ eb2,
    const float* __restrict__ nw1, const float* __restrict__ nb1,
    const float* __restrict__ nw2, const float* __restrict__ nb2) {
    extern __shared__ float sm[];
    int tid = threadIdx.x;
    int half = tid >> 8, th = tid & 255;
    int lane = tid & 31, wh = (tid >> 5) & 7;

    float* H = sm + half * HALF_FLOATS;
    float* sATs = H;
    float* sNTs = H + 1536;
    float* sPart = H + 3072;
    float* sPi = H + 7168;
    float* sPn = H + 7680;
    float* sAdj2 = H + 8192;
    float* s_rs = H + 10240;
    float* sX = H + 10248;

    int vb = blockIdx.x * 2 + half;   // virtual CTA: rows vb*4 .. vb*4+3
    int b = vb >> 6;                  // batch (64 vCTAs per batch)
    int il0 = (vb & 63) * 4;          // local i base within batch
    unsigned tgt = 0;

    // ================= setup: Wc/cb producers, arrive, local setup, wait =========
    if (vb < 96) {   // Wc[l] rows r4*4..+3 = ew2[l] @ nw1b[l]
        int l = vb / 32, r4 = vb % 32;
#pragma unroll
        for (int q = 0; q < 2; q++) {
            int idx = q * 256 + th;
            int r = idx >> 7, k = idx & 127;
            float v = ew2[l * 16384 + (r4 * 4 + r) * 128 + k];
            *(float2*)(sATs + k * 12 + 2 * r) = make_float2(v, v);
        }
        barh(half);
        u64 acc[4][2] = {};
        gemm_h(sATs, nw1 + l * 32768 + 16384, lane, wh, acc);
        store_part_h(sPart, acc, lane, wh);
        barh(half);
#pragma unroll
        for (int q = 0; q < 2; q++) {
            int idx = q * 256 + th;
            int r = idx >> 7, c = idx & 127;
            g_Wc[l][(r4 * 4 + r) * 128 + c] = reduce8_h(sPart, idx);
        }
    } else if (vb == 96) {
        for (int idx = th; idx < 384; idx += 256) {
            int l = idx >> 7, c = idx & 127;
            const float* e2 = eb2 + l * 128;
            const float* W = nw1 + l * 32768 + 16384 + c;
            float s = 0.f;
#pragma unroll 8
            for (int m = 0; m < 128; m++) s = fmaf(e2[m], W[m * 128], s);
            g_cb[l][c] = s;
        }
    }
    vbar_arrive(0, th, half, tgt);

    // ---- per-half local setup (overlapped with other vCTAs' Wc work) ----
#pragma unroll
    for (int q = 0; q < 2; q++) sX[q * 256 + th] = nf[vb * 512 + q * 256 + th];
    const float* adjb = adj + (size_t)(b * 256 + il0) * 256;
#pragma unroll
    for (int e = 0; e < 4; e++) {
        int idx = e * 256 + th;
        int r = idx >> 8, j = idx & 255;
        float v = adjb[r * 256 + j];
        *(float2*)(sAdj2 + j * 8 + 2 * r) = make_float2(v, v);
    }
    if (wh < 4) {
        float s = 0.f;
        const float* row = adjb + wh * 256;
#pragma unroll
        for (int j = lane; j < 256; j += 32) s += row[j];
#pragma unroll
        for (int o = 16; o; o >>= 1) s += __shfl_xor_sync(~0u, s, o);
        if (!lane) s_rs[wh] = s;
    }
    vbar_wait(0, th, half, tgt);

    // ================= layers =================
    for (int l = 0; l < L_; l++) {
        float* Pbuf = g_P[l & 1];
        const float* ew1l = ew1 + l * 32768;

#pragma unroll
        for (int q = 0; q < 2; q++) {              // sX -> dup'd sATs
            int idx = q * 256 + th;
            int r = idx >> 7, k = idx & 127;
            float v = sX[idx];
            *(float2*)(sATs + k * 12 + 2 * r) = make_float2(v, v);
        }
        barh(half);

        // ---- Pj = x @ ew1b -> global, then ARRIVE ----
        {
            u64 acc[4][2] = {};
            gemm_h(sATs, ew1l + 16384, lane, wh, acc);
            store_part_h(sPart, acc, lane, wh);
            barh(half);
#pragma unroll
            for (int q = 0; q < 2; q++) {
                int idx = q * 256 + th;
                int r = idx >> 7, c = idx & 127;
                Pbuf[(vb * 4 + r) * 128 + c] = reduce8_h(sPart, idx);
            }
        }
        vbar_arrive(1 + l, th, half, tgt);         // Pj published (barh inside)

        // ---- merged: [Pi|Pn] = x @ [ew1a | nw1a] (hidden behind barrier) ----
        {
            int cg = wh & 1, mkq = wh >> 1;
            u64 acc[4][2] = {};
            gemm_mh(sATs, cg ? (nw1 + l * 32768) : ew1l, lane, mkq, acc);
            float* o = sPart + mkq * 1024 + cg * 128 + lane * 4;
#pragma unroll
            for (int r = 0; r < 4; r++) {
                float v0, v1, v2, v3;
                upk(acc[r][0], v0, v1); upk(acc[r][1], v2, v3);
                *(float4*)(o + r * 256) = make_float4(v0, v1, v2, v3);
            }
            barh(half);
#pragma unroll
            for (int q = 0; q < 4; q++) {
                int idx = q * 256 + th;
                int r = idx >> 8, c = idx & 255;
                float v = 0.f;
#pragma unroll
                for (int p = 0; p < 4; p++) v += sPart[p * 1024 + idx];
                if (c < 128) sPi[r * 128 + c] = v + eb1[l * 128 + c];
                else         sPn[r * 128 + (c - 128)] = v + nb1[l * 128 + (c - 128)];
            }
        }
        vbar_wait(1 + l, th, half, tgt);   // all Pj visible; sPi/sPn complete

        // ---- agg: direct LDG.cg from Pbuf ----
        {
            u64 xi[4][2], aacc[4][2] = {};
#pragma unroll
            for (int q = 0; q < 4; q++) {
                ulonglong2 v = *(const ulonglong2*)(sPi + q * 128 + lane * 4);
                xi[q][0] = v.x; xi[q][1] = v.y;
            }
            agg_h(Pbuf + b * 32768, sAdj2, xi, aacc, lane, wh);
            store_part_h(sPart, aacc, lane, wh);
        }
        barh(half);
#pragma unroll
        for (int q = 0; q < 2; q++) {               // reduce agg -> dup'd sATs
            int idx = q * 256 + th;
            int r = idx >> 7, c = idx & 127;
            float v = reduce8_h(sPart, idx);
            *(float2*)(sATs + c * 12 + 2 * r) = make_float2(v, v);
        }
        barh(half);

        // ---- nh = relu(Pn + agg@Wc + rs*cb) ----
        {
            u64 acc[4][2] = {};
            gemm_h(sATs, g_Wc[l], lane, wh, acc);
            store_part_h(sPart, acc, lane, wh);
            barh(half);
#pragma unroll
            for (int q = 0; q < 2; q++) {
                int idx = q * 256 + th;
                int r = idx >> 7, c = idx & 127;
                float v = reduce8_h(sPart, idx) + sPn[idx] + s_rs[r] * g_cb[l][c];
                v = fmaxf(v, 0.f);
                *(float2*)(sNTs + c * 12 + 2 * r) = make_float2(v, v);
            }
            barh(half);
        }

        // ---- x += nh @ nw2 + nb2 ----
        {
            u64 acc[4][2] = {};
            gemm_h(sNTs, nw2 + l * 16384, lane, wh, acc);
            store_part_h(sPart, acc, lane, wh);
            barh(half);
#pragma unroll
            for (int q = 0; q < 2; q++) {
                int idx = q * 256 + th;
                int c = idx & 127;
                float v = sX[idx] + reduce8_h(sPart, idx) + nb2[l * 128 + c];
                sX[idx] = v;
                if (l == L_ - 1) x[vb * 512 + idx] = v;
            }
            barh(half);
        }
    }
}

// ---------------- launch ----------------
extern "C" void kernel_launch(void* const* d_in, const int* in_sizes, int n_in,
                              void* d_out, int out_size) {
    const float* nf  = (const float*)d_in[0];
    const float* adj = (const float*)d_in[1];
    const float* ew1 = (const float*)d_in[2];
    const float* eb1 = (const float*)d_in[3];
    const float* ew2 = (const float*)d_in[4];
    const float* eb2 = (const float*)d_in[5];
    const float* nw1 = (const float*)d_in[6];
    const float* nb1 = (const float*)d_in[7];
    const float* nw2 = (const float*)d_in[8];
    const float* nb2 = (const float*)d_in[9];
    float* x = (float*)d_out;

    const int SMEM = SMEM_FLOATS * 4;   // 86080 B
    cudaFuncSetAttribute(k_main, cudaFuncAttributeMaxDynamicSharedMemorySize, SMEM);
    k_main<<<NB, NT, SMEM>>>(x, nf, adj, ew1, eb1, ew2, eb2, nw1, nb1, nw2, nb2);
}

// round 14
// speedup vs baseline: 1.0863x; 1.0863x over previous
#include <cuda_runtime.h>
#include <cstdint>

typedef unsigned long long u64;
#define DEV static __device__ __forceinline__

static constexpr int L_ = 3;
static constexpr int NB = 128;   // 128 CTAs, 8 rows each
static constexpr int NT = 512;   // 16 warps

// ---------------- device globals ----------------
__device__ float g_P[2][1024 * 128];   // double-buffered Pj
__device__ float g_Wc[L_][128 * 128];  // ew2 @ nw1b
__device__ float g_cb[L_][128];        // eb2 @ nw1b
__device__ unsigned g_bar[4];          // monotonic barrier counters (replay-safe)

// ---------------- f32x2 helpers ----------------
DEV u64 pk(float lo, float hi) {
    u64 r; asm("mov.b64 %0,{%1,%2};" : "=l"(r) : "f"(lo), "f"(hi)); return r;
}
DEV void upk(u64 v, float& lo, float& hi) {
    asm("mov.b64 {%0,%1},%2;" : "=f"(lo), "=f"(hi) : "l"(v));
}
DEV u64 add2(u64 a, u64 b) {
    u64 r; asm("add.rn.f32x2 %0,%1,%2;" : "=l"(r) : "l"(a), "l"(b)); return r;
}
DEV u64 fma2(u64 a, u64 b, u64 c) {
    u64 r; asm("fma.rn.f32x2 %0,%1,%2,%3;" : "=l"(r) : "l"(a), "l"(b), "l"(c)); return r;
}
DEV u64 relu2(u64 v) {
    float lo, hi; upk(v, lo, hi);
    return pk(fmaxf(lo, 0.f), fmaxf(hi, 0.f));
}

// ---------------- split grid barrier (monotonic counters; replay-safe) ----------------
DEV unsigned ld_acq(const unsigned* p) {
    unsigned v;
    asm volatile("ld.acquire.gpu.global.u32 %0,[%1];" : "=r"(v) : "l"(p) : "memory");
    return v;
}
DEV void bar_arrive(int bidx, int tid, unsigned* sT) {
    __syncthreads();
    if (tid == 0) {
        __threadfence();
        unsigned t = atomicAdd(&g_bar[bidx], 1u);
        *sT = (t / (unsigned)NB + 1u) * (unsigned)NB;
    }
}
DEV void bar_wait(int bidx, int tid, unsigned* sT) {
    __syncthreads();
    if (tid == 0) {
        unsigned target = *sT;
        while (ld_acq(&g_bar[bidx]) < target) { __nanosleep(64); }
        __threadfence();
    }
    __syncthreads();
}

// ---------------- r=4 k-split-8 GEMM, W direct from global via __ldg --------------
// warp = (rg = w&1, kq = w>>1 of 8, 16 k each), lane = 4 cols.
// dup'd A layout: ATs[k*20 + 2r] = ATs[k*20+2r+1] = A[r][k]
DEV void gemm_g(const float* __restrict__ ATs, const float* __restrict__ W,
                int lane, int rg, int kq, u64 acc[4][2]) {
    const float* ap = ATs + kq * 16 * 20 + rg * 8;
    const float* wp = W + kq * 16 * 128 + lane * 4;
#pragma unroll
    for (int k = 0; k < 16; k++) {
        ulonglong2 wv = __ldg((const ulonglong2*)(wp + k * 128));
        ulonglong2 a01 = *(const ulonglong2*)(ap + k * 20);
        ulonglong2 a23 = *(const ulonglong2*)(ap + k * 20 + 4);
        acc[0][0] = fma2(a01.x, wv.x, acc[0][0]);
        acc[0][1] = fma2(a01.x, wv.y, acc[0][1]);
        acc[1][0] = fma2(a01.y, wv.x, acc[1][0]);
        acc[1][1] = fma2(a01.y, wv.y, acc[1][1]);
        acc[2][0] = fma2(a23.x, wv.x, acc[2][0]);
        acc[2][1] = fma2(a23.x, wv.y, acc[2][1]);
        acc[3][0] = fma2(a23.y, wv.x, acc[3][0]);
        acc[3][1] = fma2(a23.y, wv.y, acc[3][1]);
    }
}

// ---------------- merged 8x256 GEMM: warp=(cg2,rg2,kq4), 32 k each, W via __ldg ----
DEV void gemm_m_g(const float* __restrict__ ATs, const float* __restrict__ W,
                  int lane, int rg, int kq, u64 acc[4][2]) {
    const float* ap = ATs + kq * 32 * 20 + rg * 8;
    const float* wp = W + kq * 32 * 128 + lane * 4;
#pragma unroll 16
    for (int k = 0; k < 32; k++) {
        ulonglong2 wv = __ldg((const ulonglong2*)(wp + k * 128));
        ulonglong2 a01 = *(const ulonglong2*)(ap + k * 20);
        ulonglong2 a23 = *(const ulonglong2*)(ap + k * 20 + 4);
        acc[0][0] = fma2(a01.x, wv.x, acc[0][0]);
        acc[0][1] = fma2(a01.x, wv.y, acc[0][1]);
        acc[1][0] = fma2(a01.y, wv.x, acc[1][0]);
        acc[1][1] = fma2(a01.y, wv.y, acc[1][1]);
        acc[2][0] = fma2(a23.x, wv.x, acc[2][0]);
        acc[2][1] = fma2(a23.x, wv.y, acc[2][1]);
        acc[3][0] = fma2(a23.y, wv.x, acc[3][0]);
        acc[3][1] = fma2(a23.y, wv.y, acc[3][1]);
    }
}

DEV void store_part8(float* sPart, const u64 acc[4][2], int lane, int rg, int kq) {
    float* o = sPart + kq * 1024 + rg * 4 * 128 + lane * 4;
#pragma unroll
    for (int r = 0; r < 4; r++) {
        float v0, v1, v2, v3;
        upk(acc[r][0], v0, v1); upk(acc[r][1], v2, v3);
        *(float4*)(o + r * 128) = make_float4(v0, v1, v2, v3);
    }
}

DEV float reduce8(const float* __restrict__ sPart, int idx) {
    float v = 0.f;
#pragma unroll
    for (int p = 0; p < 8; p++) v += sPart[p * 1024 + idx];
    return v;
}

// u64 pair-reduce: f0 = even float offset of the pair; partial stride 1024
DEV u64 reduce8_2(const float* __restrict__ sPart, int f0) {
    u64 p0 = *(const u64*)(sPart + f0);
    u64 p1 = *(const u64*)(sPart + f0 + 1024);
    u64 p2 = *(const u64*)(sPart + f0 + 2048);
    u64 p3 = *(const u64*)(sPart + f0 + 3072);
    u64 p4 = *(const u64*)(sPart + f0 + 4096);
    u64 p5 = *(const u64*)(sPart + f0 + 5120);
    u64 p6 = *(const u64*)(sPart + f0 + 6144);
    u64 p7 = *(const u64*)(sPart + f0 + 7168);
    return add2(add2(add2(p0, p1), add2(p2, p3)), add2(add2(p4, p5), add2(p6, p7)));
}

// u64 pair-reduce over 4 partials with stride 2048 (merged GEMM)
DEV u64 reduce4_2(const float* __restrict__ sPart, int f0) {
    u64 p0 = *(const u64*)(sPart + f0);
    u64 p1 = *(const u64*)(sPart + f0 + 2048);
    u64 p2 = *(const u64*)(sPart + f0 + 4096);
    u64 p3 = *(const u64*)(sPart + f0 + 6144);
    return add2(add2(p0, p1), add2(p2, p3));
}

// ---------------- agg via direct LDG.cg: warp=(ig2,jq8), 4i x 4d, 32 j ----------
DEV void agg_ldg(const float* __restrict__ Pjb, const float* __restrict__ sAdj2,
                 const u64 xi[4][2], u64 acc[4][2], int lane, int ig, int jq) {
    const float* pj = Pjb + jq * 32 * 128 + lane * 4;
    const float* ad = sAdj2 + jq * 32 * 16 + ig * 8;
#pragma unroll 8
    for (int jj = 0; jj < 32; jj++) {
        ulonglong2 xj = __ldcg((const ulonglong2*)(pj + jj * 128));
        ulonglong2 a01 = *(const ulonglong2*)(ad + jj * 16);
        ulonglong2 a23 = *(const ulonglong2*)(ad + jj * 16 + 4);
        u64 t;
        t = relu2(add2(xi[0][0], xj.x)); acc[0][0] = fma2(t, a01.x, acc[0][0]);
        t = relu2(add2(xi[0][1], xj.y)); acc[0][1] = fma2(t, a01.x, acc[0][1]);
        t = relu2(add2(xi[1][0], xj.x)); acc[1][0] = fma2(t, a01.y, acc[1][0]);
        t = relu2(add2(xi[1][1], xj.y)); acc[1][1] = fma2(t, a01.y, acc[1][1]);
        t = relu2(add2(xi[2][0], xj.x)); acc[2][0] = fma2(t, a23.x, acc[2][0]);
        t = relu2(add2(xi[2][1], xj.y)); acc[2][1] = fma2(t, a23.x, acc[2][1]);
        t = relu2(add2(xi[3][0], xj.x)); acc[3][0] = fma2(t, a23.y, acc[3][0]);
        t = relu2(add2(xi[3][1], xj.y)); acc[3][1] = fma2(t, a23.y, acc[3][1]);
    }
}

// ---------------- smem layout (floats) ----------------
// sPart 0 (8192) | sATs 8192 (2560) | sNTs 10752 (2560) | sPi 13312 (1024)
// sPn 14336 (1024) | sAdj2 15360 (4096) | s_rs 19456 (8) | sX 19464 (1024)
// sBarT 20488 (1)
static constexpr int SMEM_FLOATS = 20489;   // 81956 B

__global__ void __launch_bounds__(NT, 1) k_main(
    float* __restrict__ x, const float* __restrict__ nf, const float* __restrict__ adj,
    const float* __restrict__ ew1, const float* __restrict__ eb1,
    const float* __restrict__ ew2, const float* __restrict__ eb2,
    const float* __restrict__ nw1, const float* __restrict__ nb1,
    const float* __restrict__ nw2, const float* __restrict__ nb2) {
    extern __shared__ float sm[];
    float* sPart = sm;
    float* sATs = sm + 8192;
    float* sNTs = sm + 10752;
    float* sPi = sm + 13312;
    float* sPn = sm + 14336;
    float* sAdj2 = sm + 15360;
    float* s_rs = sm + 19456;
    float* sX = sm + 19464;
    unsigned* sBarT = (unsigned*)(sm + 20488);

    int tid = threadIdx.x, lane = tid & 31, w = tid >> 5;
    int rb = blockIdx.x;        // rows rb*8 .. rb*8+7
    int b = rb >> 5;            // batch
    int il0 = (rb & 31) * 8;    // local i base in batch
    int rg = w & 1, kq = w >> 1;              // r4k8 roles
    int mcg = w & 1, mrg = (w >> 1) & 1, mkq = w >> 2;   // merged-GEMM roles
    int ig = w & 1, jq = w >> 1;              // agg roles
    int rr = tid >> 7, cc = tid & 127;        // reduce/epilogue roles
    int pr = tid >> 6;                        // pair-epilogue row
    int pc = (2 * tid) & 127;                 // pair-epilogue col0

    // ================= setup: produce Wc/cb, arrive, local setup, wait ==========
    if (rb < 48) {   // Wc[l] = ew2[l] @ nw1b[l]
        int l = rb / 16, r8 = rb % 16;
#pragma unroll
        for (int q = 0; q < 2; q++) {
            int idx = q * 512 + tid;
            int r = idx >> 7, k = idx & 127;
            float v = ew2[l * 16384 + (r8 * 8 + r) * 128 + k];
            *(float2*)(sATs + k * 20 + 2 * r) = make_float2(v, v);
        }
        __syncthreads();
        u64 acc[4][2] = {};
        gemm_g(sATs, nw1 + l * 32768 + 16384, lane, rg, kq, acc);
        store_part8(sPart, acc, lane, rg, kq);
        __syncthreads();
        *(u64*)(g_Wc[l] + (r8 * 8 + pr) * 128 + pc) = reduce8_2(sPart, 2 * tid);
    } else if (rb == 48) {
        if (tid < 384) {
            int l = tid >> 7, c = tid & 127;
            const float* e2 = eb2 + l * 128;
            const float* W = nw1 + l * 32768 + 16384 + c;
            float s = 0.f;
#pragma unroll 8
            for (int m = 0; m < 128; m++) s = fmaf(e2[m], W[m * 128], s);
            g_cb[l][c] = s;
        }
    }
    bar_arrive(0, tid, sBarT);

    // ---- CTA-local setup, overlapped with other CTAs' Wc work ----
#pragma unroll
    for (int q = 0; q < 2; q++) sX[q * 512 + tid] = nf[rb * 1024 + q * 512 + tid];
    const float* adjb = adj + (size_t)(b * 256 + il0) * 256;
#pragma unroll
    for (int e = 0; e < 4; e++) {
        int idx = e * 512 + tid;
        int r = idx >> 8, j = idx & 255;
        float v = adjb[r * 256 + j];
        *(float2*)(sAdj2 + j * 16 + 2 * r) = make_float2(v, v);
    }
    if (w < 8) {
        float s = 0.f;
        const float* row = adjb + w * 256;
#pragma unroll
        for (int j = lane; j < 256; j += 32) s += row[j];
#pragma unroll
        for (int o = 16; o; o >>= 1) s += __shfl_xor_sync(~0u, s, o);
        if (!lane) s_rs[w] = s;
    }
    // pre-loop: dup'd sATs from sX (own values; no sync needed before)
#pragma unroll
    for (int q = 0; q < 2; q++) {
        int idx = q * 512 + tid;
        int r = idx >> 7, k = idx & 127;
        float v = sX[idx];
        *(float2*)(sATs + k * 20 + 2 * r) = make_float2(v, v);
    }
    bar_wait(0, tid, sBarT);   // also orders sATs init before layer-0 GEMM reads

    // ================= layers =================
    for (int l = 0; l < L_; l++) {
        float* Pbuf = g_P[l & 1];
        const float* ew1l = ew1 + l * 32768;

        // ---- Pj = x @ ew1b -> global (stcg), then ARRIVE ----
        {
            u64 acc[4][2] = {};
            gemm_g(sATs, ew1l + 16384, lane, rg, kq, acc);
            store_part8(sPart, acc, lane, rg, kq);
            __syncthreads();
            __stcg((u64*)(Pbuf + (rb * 8 + pr) * 128 + pc), reduce8_2(sPart, 2 * tid));
        }
        bar_arrive(1 + l, tid, sBarT);             // Pj published (sync inside)

        // ---- merged: [Pi|Pn] = x @ [ew1a | nw1a] + [eb1|nb1] (hidden behind barrier) ----
        {
            u64 acc[4][2] = {};
            gemm_m_g(sATs, mcg ? (nw1 + l * 32768) : ew1l, lane, mrg, mkq, acc);
            {   // store to sPart[kq][8r][256c]
                float* o = sPart + mkq * 2048 + mrg * 4 * 256 + mcg * 128 + lane * 4;
#pragma unroll
                for (int r = 0; r < 4; r++) {
                    float v0, v1, v2, v3;
                    upk(acc[r][0], v0, v1); upk(acc[r][1], v2, v3);
                    *(float4*)(o + r * 256) = make_float4(v0, v1, v2, v3);
                }
            }
            __syncthreads();
#pragma unroll
            for (int q = 0; q < 2; q++) {
                int i = q * 512 + tid;             // pair index 0..1023
                int f0 = 2 * i;
                int r = f0 >> 8, c = f0 & 255;
                u64 v = reduce4_2(sPart, f0);
                if (c < 128) {
                    u64 bb = *(const u64*)(eb1 + l * 128 + c);
                    *(u64*)(sPi + r * 128 + c) = add2(v, bb);
                } else {
                    int c2 = c - 128;
                    u64 bb = *(const u64*)(nb1 + l * 128 + c2);
                    *(u64*)(sPn + r * 128 + c2) = add2(v, bb);
                }
            }
        }
        bar_wait(1 + l, tid, sBarT);   // all Pj visible; sPi/sPn complete

        // ---- agg: direct LDG.cg from Pbuf ----
        {
            u64 xi[4][2], aacc[4][2] = {};
#pragma unroll
            for (int q = 0; q < 4; q++) {
                ulonglong2 v = *(const ulonglong2*)(sPi + (ig * 4 + q) * 128 + lane * 4);
                xi[q][0] = v.x; xi[q][1] = v.y;
            }
            agg_ldg(Pbuf + b * 32768, sAdj2, xi, aacc, lane, ig, jq);
            float* o = sPart + jq * 1024 + ig * 4 * 128 + lane * 4;
#pragma unroll
            for (int q = 0; q < 4; q++) {
                float v0, v1, v2, v3;
                upk(aacc[q][0], v0, v1); upk(aacc[q][1], v2, v3);
                *(float4*)(o + q * 128) = make_float4(v0, v1, v2, v3);
            }
        }
        __syncthreads();
#pragma unroll
        for (int q = 0; q < 2; q++) {               // reduce agg -> dup'd sATs
            int idx = q * 512 + tid;
            float v = reduce8(sPart, idx);
            *(float2*)(sATs + cc * 20 + 2 * (rr + q * 4)) = make_float2(v, v);
        }
        __syncthreads();

        // ---- nh = relu(Pn + agg@Wc + rs*cb) ----
        {
            u64 acc[4][2] = {};
            gemm_g(sATs, g_Wc[l], lane, rg, kq, acc);
            store_part8(sPart, acc, lane, rg, kq);
            __syncthreads();
            float cbv = g_cb[l][cc];
#pragma unroll
            for (int q = 0; q < 2; q++) {
                int idx = q * 512 + tid;
                int r = rr + q * 4;
                float v = reduce8(sPart, idx) + sPn[r * 128 + cc] + s_rs[r] * cbv;
                v = fmaxf(v, 0.f);
                *(float2*)(sNTs + cc * 20 + 2 * r) = make_float2(v, v);
            }
            __syncthreads();
        }

        // ---- x += nh @ nw2 + nb2 (fused: also writes next layer's dup'd sATs) ----
        {
            u64 acc[4][2] = {};
            gemm_g(sNTs, nw2 + l * 16384, lane, rg, kq, acc);
            store_part8(sPart, acc, lane, rg, kq);
            __syncthreads();
            float bv = nb2[l * 128 + cc];
#pragma unroll
            for (int q = 0; q < 2; q++) {
                int idx = q * 512 + tid;
                int r = rr + q * 4;
                float v = sX[idx] + reduce8(sPart, idx) + bv;
                sX[idx] = v;
                *(float2*)(sATs + cc * 20 + 2 * r) = make_float2(v, v);
                if (l == L_ - 1) x[rb * 1024 + idx] = v;
            }
            __syncthreads();   // sATs/sX/sPart stable before next layer
        }
    }
}

// ---------------- launch ----------------
extern "C" void kernel_launch(void* const* d_in, const int* in_sizes, int n_in,
                              void* d_out, int out_size) {
    const float* nf  = (const float*)d_in[0];
    const float* adj = (const float*)d_in[1];
    const float* ew1 = (const float*)d_in[2];
    const float* eb1 = (const float*)d_in[3];
    const float* ew2 = (const float*)d_in[4];
    const float* eb2 = (const float*)d_in[5];
    const float* nw1 = (const float*)d_in[6];
    const float* nb1 = (const float*)d_in[7];
    const float* nw2 = (const float*)d_in[8];
    const float* nb2 = (const float*)d_in[9];
    float* x = (float*)d_out;

    const int SMEM = SMEM_FLOATS * 4;   // 81956 B
    cudaFuncSetAttribute(k_main, cudaFuncAttributeMaxDynamicSharedMemorySize, SMEM);
    k_main<<<NB, NT, SMEM>>>(x, nf, adj, ew1, eb1, ew2, eb2, nw1, nb1, nw2, nb2);
}